// round 6
// baseline (speedup 1.0000x reference)
#include <cuda_runtime.h>

// GCNRFPEncode — CSR gather-side aggregation, no float atomics.
// out = BN( 0.5*invsq[s]*sum_{dst in adj[s]} g[dst] + 0.5*deg[s]^1.5*g[s] )
// g[v] = rsqrt(deg[v]) * (X[v]@W + b)

#define FF 128
#define HH 64
#define NMAX 100000
#define EMAX 2000000
#define NBMAX 512           // max scan blocks (ceil(NMAX/256) = 391)
#define BN_EPS 0.001f

__device__ int   g_degi[NMAX];
__device__ int   g_off[NMAX + 1];
__device__ int   g_cursor[NMAX];
__device__ int   g_adj[EMAX];
__device__ int   g_bsum[NBMAX];
__device__ int   g_bbase[NBMAX];
__device__ float g_g[(size_t)NMAX * HH];

// ---------------- packed f32x2 helpers ------------------------------------------
__device__ __forceinline__ unsigned long long ffma2(unsigned long long a,
                                                    unsigned long long b,
                                                    unsigned long long c) {
    unsigned long long d;
    asm("fma.rn.f32x2 %0, %1, %2, %3;" : "=l"(d) : "l"(a), "l"(b), "l"(c));
    return d;
}
__device__ __forceinline__ float2 unpack2(unsigned long long v) {
    float2 r;
    asm("mov.b64 {%0, %1}, %2;" : "=f"(r.x), "=f"(r.y) : "l"(v));
    return r;
}

// ---------------- zero degree counters ------------------------------------------
__global__ void k_zero(int N) {
    int t = blockIdx.x * blockDim.x + threadIdx.x;
    if (t < N) g_degi[t] = 0;
}

// ---------------- degree count (int RED) ----------------------------------------
__global__ void k_deg(const int2* __restrict__ edge, int E) {
    int t = blockIdx.x * blockDim.x + threadIdx.x;
    if (t < E) atomicAdd(&g_degi[edge[t].x], 1);
}

// ---------------- phase 1: per-block sums (coalesced) ----------------------------
__global__ __launch_bounds__(256) void k_bsum(int N) {
    __shared__ int sw[8];
    int t = blockIdx.x * 256 + threadIdx.x;
    int d = (t < N) ? g_degi[t] : 0;
    int v = d;
#pragma unroll
    for (int o = 16; o > 0; o >>= 1) v += __shfl_down_sync(0xffffffffu, v, o);
    if ((threadIdx.x & 31) == 0) sw[threadIdx.x >> 5] = v;
    __syncthreads();
    if (threadIdx.x < 8) {
        int s = sw[threadIdx.x];
#pragma unroll
        for (int o = 4; o > 0; o >>= 1) s += __shfl_down_sync(0xffu, s, o);
        if (threadIdx.x == 0) g_bsum[blockIdx.x] = s;
    }
}

// ---------------- phase 2: scan block sums (1 block, 512 lanes) ------------------
__global__ __launch_bounds__(512) void k_bscan(int NB) {
    __shared__ int sp[512];
    int t = threadIdx.x;
    int v = (t < NB) ? g_bsum[t] : 0;
    sp[t] = v;
    __syncthreads();
#pragma unroll
    for (int o = 1; o < 512; o <<= 1) {
        int u = (t >= o) ? sp[t - o] : 0;
        __syncthreads();
        sp[t] += u;
        __syncthreads();
    }
    if (t < NB) g_bbase[t] = sp[t] - v;   // exclusive base for block t
}

// ---------------- phase 3: local exclusive scan + base -> g_off/g_cursor ---------
__global__ __launch_bounds__(256) void k_off(int N, int E) {
    __shared__ int sw[8];
    int tid = threadIdx.x;
    int t = blockIdx.x * 256 + tid;
    int d = (t < N) ? g_degi[t] : 0;
    int lane = tid & 31, w = tid >> 5;
    // inclusive warp scan
    int v = d;
#pragma unroll
    for (int o = 1; o < 32; o <<= 1) {
        int u = __shfl_up_sync(0xffffffffu, v, o);
        if (lane >= o) v += u;
    }
    if (lane == 31) sw[w] = v;
    __syncthreads();
    if (tid < 8) {
        int s = sw[tid];
#pragma unroll
        for (int o = 1; o < 8; o <<= 1) {
            int u = __shfl_up_sync(0xffu, s, o);
            if (tid >= o) s += u;
        }
        sw[tid] = s;
    }
    __syncthreads();
    int base = g_bbase[blockIdx.x] + (w ? sw[w - 1] : 0);
    int excl = base + v - d;
    if (t < N) {
        g_off[t] = excl;
        g_cursor[t] = excl;
    }
    if (blockIdx.x == 0 && tid == 0) g_off[N] = E;
}

// ---------------- scatter edges into CSR buckets ---------------------------------
__global__ void k_scatter(const int2* __restrict__ edge, int E) {
    int t = blockIdx.x * blockDim.x + threadIdx.x;
    if (t < E) {
        int2 sd = edge[t];
        int p = atomicAdd(&g_cursor[sd.x], 1);
        g_adj[p] = sd.y;
    }
}

// ---------------- GEMM: g = (X@W + b) * rsqrt(deg) -------------------------------
extern __shared__ unsigned long long g_smem[];

__global__ __launch_bounds__(256, 2) void k_gemm(const float* __restrict__ X,
                                                 const float* __restrict__ W,
                                                 const float* __restrict__ b,
                                                 int N) {
    ulonglong2* sX = (ulonglong2*)g_smem;            // 128 rows x 32 k4 = 64 KB
    ulonglong2* sW = sX + 128 * 32;                  // 32 k4 x 64 col  = 32 KB
    float4* sX4 = (float4*)sX;
    float4* sW4 = (float4*)sW;

    int tid = threadIdx.x;
    int row0 = blockIdx.x * 128;
    int maxr = N - row0;

    const float4* Xg = (const float4*)X + (size_t)row0 * 32;
#pragma unroll
    for (int it = 0; it < 16; it++) {
        int i = tid + it * 256;
        int r = i >> 5;
        float4 v = make_float4(0.f, 0.f, 0.f, 0.f);
        if (r < maxr) v = Xg[i];
        sX4[i] = v;
    }
#pragma unroll
    for (int it = 0; it < 8; it++) {
        int j = tid + it * 256;
        int col = j & 63, k4 = j >> 6;
        float4 w;
        w.x = W[(4 * k4 + 0) * HH + col];
        w.y = W[(4 * k4 + 1) * HH + col];
        w.z = W[(4 * k4 + 2) * HH + col];
        w.w = W[(4 * k4 + 3) * HH + col];
        sW4[j] = w;
    }
    __syncthreads();

    int tx = tid & 15;
    int ty = tid >> 4;
    int r0 = ty * 8;

    float bv[4];
#pragma unroll
    for (int c = 0; c < 4; c++) bv[c] = b[tx + 16 * c];

    unsigned long long acc[8][4];
#pragma unroll
    for (int r = 0; r < 8; r++)
#pragma unroll
        for (int c = 0; c < 4; c++) acc[r][c] = 0ull;

#pragma unroll 2
    for (int k4 = 0; k4 < 32; k4++) {
        ulonglong2 w0 = sW[k4 * 64 + tx];
        ulonglong2 w1 = sW[k4 * 64 + tx + 16];
        ulonglong2 w2 = sW[k4 * 64 + tx + 32];
        ulonglong2 w3 = sW[k4 * 64 + tx + 48];
#pragma unroll
        for (int r = 0; r < 8; r++) {
            ulonglong2 x = sX[(r0 + r) * 32 + k4];
            acc[r][0] = ffma2(x.x, w0.x, acc[r][0]);
            acc[r][1] = ffma2(x.x, w1.x, acc[r][1]);
            acc[r][2] = ffma2(x.x, w2.x, acc[r][2]);
            acc[r][3] = ffma2(x.x, w3.x, acc[r][3]);
            acc[r][0] = ffma2(x.y, w0.y, acc[r][0]);
            acc[r][1] = ffma2(x.y, w1.y, acc[r][1]);
            acc[r][2] = ffma2(x.y, w2.y, acc[r][2]);
            acc[r][3] = ffma2(x.y, w3.y, acc[r][3]);
        }
    }

#pragma unroll
    for (int r = 0; r < 8; r++) {
        int row = row0 + r0 + r;
        if (row < N) {
            float is = rsqrtf((float)g_degi[row]);
            float* gp = g_g + (size_t)row * HH;
#pragma unroll
            for (int c = 0; c < 4; c++) {
                float2 p = unpack2(acc[r][c]);
                gp[tx + 16 * c] = (p.x + p.y + bv[c]) * is;
            }
        }
    }
}

// ---------------- gather + finalize (fused) --------------------------------------
// 16 threads per node; each owns a float4 feature chunk. No atomics, single write.
__global__ void k_gather(float* __restrict__ out,
                         const float* __restrict__ gamma,
                         const float* __restrict__ beta,
                         const float* __restrict__ mean,
                         const float* __restrict__ var,
                         int N) {
    int t = blockIdx.x * blockDim.x + threadIdx.x;
    int v = t >> 4, q = t & 15;
    if (v >= N) return;

    int beg = g_off[v], end = g_off[v + 1];

    float4 acc = make_float4(0.f, 0.f, 0.f, 0.f);
    int i = beg;
    for (; i + 4 <= end; i += 4) {
        int d0 = __ldg(&g_adj[i + 0]);
        int d1 = __ldg(&g_adj[i + 1]);
        int d2 = __ldg(&g_adj[i + 2]);
        int d3 = __ldg(&g_adj[i + 3]);
        float4 a0 = __ldg((const float4*)(g_g + (size_t)d0 * HH) + q);
        float4 a1 = __ldg((const float4*)(g_g + (size_t)d1 * HH) + q);
        float4 a2 = __ldg((const float4*)(g_g + (size_t)d2 * HH) + q);
        float4 a3 = __ldg((const float4*)(g_g + (size_t)d3 * HH) + q);
        acc.x += a0.x + a1.x + a2.x + a3.x;
        acc.y += a0.y + a1.y + a2.y + a3.y;
        acc.z += a0.z + a1.z + a2.z + a3.z;
        acc.w += a0.w + a1.w + a2.w + a3.w;
    }
    for (; i < end; i++) {
        int d = __ldg(&g_adj[i]);
        float4 a = __ldg((const float4*)(g_g + (size_t)d * HH) + q);
        acc.x += a.x; acc.y += a.y; acc.z += a.z; acc.w += a.w;
    }

    float dg = (float)(end - beg);
    float hs = 0.5f * rsqrtf(dg);          // 0.5 * deg^-1/2
    float sc = 0.5f * dg * sqrtf(dg);      // 0.5 * deg^1.5
    float4 gs = __ldg((const float4*)(g_g + (size_t)v * HH) + q);

    int j = q << 2;
    float sv[4] = {acc.x, acc.y, acc.z, acc.w};
    float gv[4] = {gs.x, gs.y, gs.z, gs.w};
    float o[4];
#pragma unroll
    for (int c = 0; c < 4; c++) {
        float a = hs * sv[c] + sc * gv[c];
        float scale = gamma[j + c] * rsqrtf(var[j + c] + BN_EPS);
        o[c] = (a - mean[j + c]) * scale + beta[j + c];
    }
    ((float4*)out)[t] = make_float4(o[0], o[1], o[2], o[3]);
}

// ---------------- launch ----------------------------------------------------------
extern "C" void kernel_launch(void* const* d_in, const int* in_sizes, int n_in,
                              void* d_out, int out_size) {
    const float* X     = (const float*)d_in[0];
    const float* W     = (const float*)d_in[1];
    const float* b     = (const float*)d_in[2];
    const float* gamma = (const float*)d_in[3];
    const float* beta  = (const float*)d_in[4];
    const float* mean  = (const float*)d_in[5];
    const float* var   = (const float*)d_in[6];
    const int2*  edge  = (const int2*)d_in[7];

    int N = in_sizes[0] / FF;
    int E = in_sizes[7] / 2;
    float* out = (float*)d_out;

    static const int SMEM = 96 * 1024;
    cudaFuncSetAttribute(k_gemm, cudaFuncAttributeMaxDynamicSharedMemorySize, SMEM);

    int NB = (N + 255) / 256;
    k_zero<<<(N + 255) / 256, 256>>>(N);
    k_deg<<<(E + 255) / 256, 256>>>(edge, E);
    k_bsum<<<NB, 256>>>(N);
    k_bscan<<<1, 512>>>(NB);
    k_off<<<NB, 256>>>(N, E);
    k_scatter<<<(E + 255) / 256, 256>>>(edge, E);
    k_gemm<<<(N + 127) / 128, 256, SMEM>>>(X, W, b, N);
    k_gather<<<(N * 16 + 255) / 256, 256>>>(out, gamma, beta, mean, var, N);
}

// round 7
// speedup vs baseline: 1.0003x; 1.0003x over previous
#include <cuda_runtime.h>
#include <cuda_fp16.h>

// GCNRFPEncode — CSR gather-side aggregation, no float atomics.
// out = BN( 0.5*invsq[s]*sum_{dst in adj[s]} g[dst] + 0.5*deg[s]^1.5*g[s] )
// g[v] = rsqrt(deg[v]) * (X[v]@W + b)
// Neighbor gathers read an fp16 copy of g (3% of output magnitude);
// the dominant self term reads fp32 g.

#define FF 128
#define HH 64
#define NMAX 100000
#define EMAX 2000000
#define BN_EPS 0.001f

__device__ int    g_degi[NMAX];
__device__ int    g_off[NMAX];
__device__ int    g_cursor[NMAX];
__device__ int    g_adj[EMAX];
__device__ int    g_total;
__device__ float  g_g[(size_t)NMAX * HH];
__device__ __half g_g16[(size_t)NMAX * HH];

// ---------------- packed f32x2 helpers ------------------------------------------
__device__ __forceinline__ unsigned long long ffma2(unsigned long long a,
                                                    unsigned long long b,
                                                    unsigned long long c) {
    unsigned long long d;
    asm("fma.rn.f32x2 %0, %1, %2, %3;" : "=l"(d) : "l"(a), "l"(b), "l"(c));
    return d;
}
__device__ __forceinline__ float2 unpack2(unsigned long long v) {
    float2 r;
    asm("mov.b64 {%0, %1}, %2;" : "=f"(r.x), "=f"(r.y) : "l"(v));
    return r;
}

// ---------------- zero degree counters + ticket ----------------------------------
__global__ void k_zero(int N) {
    int t = blockIdx.x * blockDim.x + threadIdx.x;
    if (t < N) g_degi[t] = 0;
    if (t == 0) g_total = 0;
}

// ---------------- degree count (int RED) ------------------------------------------
__global__ void k_deg(const int2* __restrict__ edge, int E) {
    int t = blockIdx.x * blockDim.x + threadIdx.x;
    if (t < E) atomicAdd(&g_degi[edge[t].x], 1);
}

// ---------------- offset allocation: warp scan + one atomic per warp --------------
// Ranges are contiguous per node; global ordering is irrelevant for the gather.
__global__ __launch_bounds__(256) void k_offal(int N) {
    int t = blockIdx.x * 256 + threadIdx.x;
    int lane = threadIdx.x & 31;
    int d = (t < N) ? g_degi[t] : 0;
    int v = d;
#pragma unroll
    for (int o = 1; o < 32; o <<= 1) {
        int u = __shfl_up_sync(0xffffffffu, v, o);
        if (lane >= o) v += u;
    }
    int wbase = 0;
    if (lane == 31) wbase = atomicAdd(&g_total, v);   // v@31 == warp total
    wbase = __shfl_sync(0xffffffffu, wbase, 31);
    int excl = wbase + v - d;
    if (t < N) {
        g_off[t] = excl;
        g_cursor[t] = excl;
    }
}

// ---------------- scatter edges into CSR buckets -----------------------------------
__global__ void k_scatter(const int2* __restrict__ edge, int E) {
    int t = blockIdx.x * blockDim.x + threadIdx.x;
    if (t < E) {
        int2 sd = edge[t];
        int p = atomicAdd(&g_cursor[sd.x], 1);
        g_adj[p] = sd.y;
    }
}

// ---------------- GEMM: g = (X@W + b) * rsqrt(deg), fp32 + fp16 copies -------------
extern __shared__ unsigned long long g_smem[];

__global__ __launch_bounds__(256, 2) void k_gemm(const float* __restrict__ X,
                                                 const float* __restrict__ W,
                                                 const float* __restrict__ b,
                                                 int N) {
    ulonglong2* sX = (ulonglong2*)g_smem;            // 128 rows x 32 k4 = 64 KB
    ulonglong2* sW = sX + 128 * 32;                  // 32 k4 x 64 col  = 32 KB
    float4* sX4 = (float4*)sX;
    float4* sW4 = (float4*)sW;

    int tid = threadIdx.x;
    int row0 = blockIdx.x * 128;
    int maxr = N - row0;

    const float4* Xg = (const float4*)X + (size_t)row0 * 32;
#pragma unroll
    for (int it = 0; it < 16; it++) {
        int i = tid + it * 256;
        int r = i >> 5;
        float4 v = make_float4(0.f, 0.f, 0.f, 0.f);
        if (r < maxr) v = Xg[i];
        sX4[i] = v;
    }
#pragma unroll
    for (int it = 0; it < 8; it++) {
        int j = tid + it * 256;
        int col = j & 63, k4 = j >> 6;
        float4 w;
        w.x = W[(4 * k4 + 0) * HH + col];
        w.y = W[(4 * k4 + 1) * HH + col];
        w.z = W[(4 * k4 + 2) * HH + col];
        w.w = W[(4 * k4 + 3) * HH + col];
        sW4[j] = w;
    }
    __syncthreads();

    int tx = tid & 15;
    int ty = tid >> 4;
    int r0 = ty * 8;

    float bv[4];
#pragma unroll
    for (int c = 0; c < 4; c++) bv[c] = b[tx + 16 * c];

    unsigned long long acc[8][4];
#pragma unroll
    for (int r = 0; r < 8; r++)
#pragma unroll
        for (int c = 0; c < 4; c++) acc[r][c] = 0ull;

#pragma unroll 2
    for (int k4 = 0; k4 < 32; k4++) {
        ulonglong2 w0 = sW[k4 * 64 + tx];
        ulonglong2 w1 = sW[k4 * 64 + tx + 16];
        ulonglong2 w2 = sW[k4 * 64 + tx + 32];
        ulonglong2 w3 = sW[k4 * 64 + tx + 48];
#pragma unroll
        for (int r = 0; r < 8; r++) {
            ulonglong2 x = sX[(r0 + r) * 32 + k4];
            acc[r][0] = ffma2(x.x, w0.x, acc[r][0]);
            acc[r][1] = ffma2(x.x, w1.x, acc[r][1]);
            acc[r][2] = ffma2(x.x, w2.x, acc[r][2]);
            acc[r][3] = ffma2(x.x, w3.x, acc[r][3]);
            acc[r][0] = ffma2(x.y, w0.y, acc[r][0]);
            acc[r][1] = ffma2(x.y, w1.y, acc[r][1]);
            acc[r][2] = ffma2(x.y, w2.y, acc[r][2]);
            acc[r][3] = ffma2(x.y, w3.y, acc[r][3]);
        }
    }

#pragma unroll
    for (int r = 0; r < 8; r++) {
        int row = row0 + r0 + r;
        if (row < N) {
            float is = rsqrtf((float)g_degi[row]);
            float*  gp = g_g   + (size_t)row * HH;
            __half* hp = g_g16 + (size_t)row * HH;
#pragma unroll
            for (int c = 0; c < 4; c++) {
                float2 p = unpack2(acc[r][c]);
                float val = (p.x + p.y + bv[c]) * is;
                gp[tx + 16 * c] = val;
                hp[tx + 16 * c] = __float2half_rn(val);
            }
        }
    }
}

// ---------------- gather + finalize (fused) -----------------------------------------
// 16 threads per node; each owns 4 feature cols. Neighbor rows read fp16 (8B/lane),
// self row read fp32. No atomics, single write.
__global__ void k_gather(float* __restrict__ out,
                         const float* __restrict__ gamma,
                         const float* __restrict__ beta,
                         const float* __restrict__ mean,
                         const float* __restrict__ var,
                         int N) {
    int t = blockIdx.x * blockDim.x + threadIdx.x;
    int v = t >> 4, q = t & 15;
    if (v >= N) return;

    int beg = g_off[v];
    int dgi = g_degi[v];
    int end = beg + dgi;

    float4 acc = make_float4(0.f, 0.f, 0.f, 0.f);
    int i = beg;
    for (; i + 4 <= end; i += 4) {
        int d0 = __ldg(&g_adj[i + 0]);
        int d1 = __ldg(&g_adj[i + 1]);
        int d2 = __ldg(&g_adj[i + 2]);
        int d3 = __ldg(&g_adj[i + 3]);
        uint2 u0 = __ldg((const uint2*)(g_g16 + (size_t)d0 * HH) + q);
        uint2 u1 = __ldg((const uint2*)(g_g16 + (size_t)d1 * HH) + q);
        uint2 u2 = __ldg((const uint2*)(g_g16 + (size_t)d2 * HH) + q);
        uint2 u3 = __ldg((const uint2*)(g_g16 + (size_t)d3 * HH) + q);
#pragma unroll
        for (int e = 0; e < 4; e++) {
            uint2 u = (e == 0) ? u0 : (e == 1) ? u1 : (e == 2) ? u2 : u3;
            float2 a = __half22float2(*(const __half2*)&u.x);
            float2 bq = __half22float2(*(const __half2*)&u.y);
            acc.x += a.x; acc.y += a.y; acc.z += bq.x; acc.w += bq.y;
        }
    }
    for (; i < end; i++) {
        int d = __ldg(&g_adj[i]);
        uint2 u = __ldg((const uint2*)(g_g16 + (size_t)d * HH) + q);
        float2 a = __half22float2(*(const __half2*)&u.x);
        float2 bq = __half22float2(*(const __half2*)&u.y);
        acc.x += a.x; acc.y += a.y; acc.z += bq.x; acc.w += bq.y;
    }

    float dg = (float)dgi;
    float hs = 0.5f * rsqrtf(dg);          // 0.5 * deg^-1/2
    float sc = 0.5f * dg * sqrtf(dg);      // 0.5 * deg^1.5
    float4 gs = __ldg((const float4*)(g_g + (size_t)v * HH) + q);

    int j = q << 2;
    float sv[4] = {acc.x, acc.y, acc.z, acc.w};
    float gv[4] = {gs.x, gs.y, gs.z, gs.w};
    float o[4];
#pragma unroll
    for (int c = 0; c < 4; c++) {
        float a = hs * sv[c] + sc * gv[c];
        float scale = gamma[j + c] * rsqrtf(var[j + c] + BN_EPS);
        o[c] = (a - mean[j + c]) * scale + beta[j + c];
    }
    ((float4*)out)[t] = make_float4(o[0], o[1], o[2], o[3]);
}

// ---------------- launch --------------------------------------------------------------
extern "C" void kernel_launch(void* const* d_in, const int* in_sizes, int n_in,
                              void* d_out, int out_size) {
    const float* X     = (const float*)d_in[0];
    const float* W     = (const float*)d_in[1];
    const float* b     = (const float*)d_in[2];
    const float* gamma = (const float*)d_in[3];
    const float* beta  = (const float*)d_in[4];
    const float* mean  = (const float*)d_in[5];
    const float* var   = (const float*)d_in[6];
    const int2*  edge  = (const int2*)d_in[7];

    int N = in_sizes[0] / FF;
    int E = in_sizes[7] / 2;
    float* out = (float*)d_out;

    static const int SMEM = 96 * 1024;
    cudaFuncSetAttribute(k_gemm, cudaFuncAttributeMaxDynamicSharedMemorySize, SMEM);

    k_zero<<<(N + 255) / 256, 256>>>(N);
    k_deg<<<(E + 255) / 256, 256>>>(edge, E);
    k_offal<<<(N + 255) / 256, 256>>>(N);
    k_scatter<<<(E + 255) / 256, 256>>>(edge, E);
    k_gemm<<<(N + 127) / 128, 256, SMEM>>>(X, W, b, N);
    k_gather<<<(N * 16 + 255) / 256, 256>>>(out, gamma, beta, mean, var, N);
}